// round 11
// baseline (speedup 1.0000x reference)
#include <cuda_runtime.h>

// DCN CrossLayer closed form: out = x0 * a3 + (b0+b1+b2), with
//   d_l = dot(x0, w_l), c1 = dot(b0,w1), c2 = dot(b0+b1,w2),
//   a1 = 1+d0; s1 = a1*d1+c1; a2 = a1+s1; s2 = a2*d2+c2; a3 = a2+s2.
//
// Thread-owns-feature (256 thr, thread t owns float4 chunk t of F=1024).
// ALL 8 rows' x loads front-batched (MLP_p1=8) before any reduction; two
// reduction phases (4 rows each) then run on register-resident x — phase 2
// touches no global loads at all. Batched 13-SHFL butterfly per phase with
// p ordered as id = row + 4*dot so stage-2 needs only 6 SHFLs.

#define F_DIM 1024
#define F4    256
#define RPI   4
#define ROWS_PER_BLOCK 8
#define FULL  0xffffffffu

__device__ __forceinline__ float dot4(float4 a, float4 b) {
    float acc = a.x * b.x;
    acc = fmaf(a.y, b.y, acc);
    acc = fmaf(a.z, b.z, acc);
    return fmaf(a.w, b.w, acc);
}

__device__ __forceinline__ float pair_step(float a, float b, int off, int lane) {
    const bool hi = (lane & off) != 0;
    float keep = hi ? b : a;
    float send = hi ? a : b;
    return keep + __shfl_xor_sync(FULL, send, off);
}

__global__ void __launch_bounds__(256, 4)
cross_layer_kernel(const float4* __restrict__ x,
                   const float*  __restrict__ w,   // [3,1024]
                   const float*  __restrict__ b,   // [3,1024]
                   float4* __restrict__ out)
{
    __shared__ float  sPf[2][12 * 8];  // [phase][sum_id][warp]
    __shared__ float4 sB[F4];          // b0+b1+b2 per feature chunk
    __shared__ float2 sC[8];           // (c1,c2) warp partials

    const int tid  = threadIdx.x;
    const int lane = tid & 31;
    const int wid  = tid >> 5;

    // ---- Register-resident weights at this thread's feature chunk ----
    const float4 w0 = __ldg(&((const float4*)(w))[tid]);
    const float4 w1 = __ldg(&((const float4*)(w + F_DIM))[tid]);
    const float4 w2 = __ldg(&((const float4*)(w + 2 * F_DIM))[tid]);

    // ---- Prologue: B -> smem, c1/c2 block scalars. ----
    {
        const float4 b0v = __ldg(&((const float4*)(b))[tid]);
        const float4 b1v = __ldg(&((const float4*)(b + F_DIM))[tid]);
        const float4 b2v = __ldg(&((const float4*)(b + 2 * F_DIM))[tid]);
        float4 b01, B;
        b01.x = b0v.x + b1v.x;  b01.y = b0v.y + b1v.y;
        b01.z = b0v.z + b1v.z;  b01.w = b0v.w + b1v.w;
        B.x = b01.x + b2v.x;    B.y = b01.y + b2v.y;
        B.z = b01.z + b2v.z;    B.w = b01.w + b2v.w;
        sB[tid] = B;

        float q = pair_step(dot4(b0v, w1), dot4(b01, w2), 16, lane);
#pragma unroll
        for (int o = 8; o; o >>= 1) q += __shfl_xor_sync(FULL, q, o);
        if (lane == 0)  sC[wid].x = q;
        if (lane == 16) sC[wid].y = q;
    }
    __syncthreads();

    float c1 = 0.0f, c2 = 0.0f;
#pragma unroll
    for (int i = 0; i < 8; i++) { float2 v = sC[i]; c1 += v.x; c2 += v.y; }

    const size_t base = (size_t)blockIdx.x * ROWS_PER_BLOCK * F4 + tid;
    const float4* __restrict__ xp = x + base;
    float4*       __restrict__ op = out + base;

    // ---- Front-batch ALL 8 rows (8 independent LDG.128 per thread) ----
    float4 xr[ROWS_PER_BLOCK];
#pragma unroll
    for (int r = 0; r < ROWS_PER_BLOCK; r++)
        xr[r] = __ldg(xp + r * F4);

#pragma unroll
    for (int it = 0; it < 2; it++) {
        float* __restrict__ sP = sPf[it];
        const int rb = it * RPI;

        // 12 per-thread partials, ordered id = row + 4*dot.
        float p[12];
#pragma unroll
        for (int r = 0; r < RPI; r++) {
            p[r + 0] = dot4(xr[rb + r], w0);
            p[r + 4] = dot4(xr[rb + r], w1);
            p[r + 8] = dot4(xr[rb + r], w2);
        }

        // Batched butterfly: 13 SHFLs reduce all 12 scalars.
        float u0 = pair_step(p[0],  p[1],  16, lane);
        float u1 = pair_step(p[2],  p[3],  16, lane);
        float u2 = pair_step(p[4],  p[5],  16, lane);
        float u3 = pair_step(p[6],  p[7],  16, lane);
        float u4 = pair_step(p[8],  p[9],  16, lane);
        float u5 = pair_step(p[10], p[11], 16, lane);
        float t0 = pair_step(u0, u1, 8, lane);
        float t1 = pair_step(u2, u3, 8, lane);
        float t2 = pair_step(u4, u5, 8, lane);
        float s0 = pair_step(t0, t1, 4, lane);
        float s1 = t2 + __shfl_xor_sync(FULL, t2, 4);
        float q  = pair_step(s0, s1, 2, lane);
        q += __shfl_xor_sync(FULL, q, 1);

        // Lane -> slot mapping for this tree (verified R6/R9):
        //   b1==0: slot = 4*b2 + 2*b3 + b4 ; b1==1: slot = 8 + 2*b3 + b4
        const int b4 = (lane >> 4) & 1, b3 = (lane >> 3) & 1;
        const int b2i = (lane >> 2) & 1, b1i = (lane >> 1) & 1, b0i = lane & 1;
        const int  slot   = b1i ? (8 + 2 * b3 + b4) : (4 * b2i + 2 * b3 + b4);
        const bool writer = (b0i == 0) && (b1i == 0 || b2i == 0);
        if (writer) sP[slot * 8 + wid] = q;
        __syncthreads();

        // Stage-2 per warp: lane k (k<12) sums 8 warp-partials of id k.
        float dsum = 0.0f;
        if (lane < 12) {
            const float4* pp = (const float4*)(sP + lane * 8);
            float4 aa = pp[0], bb = pp[1];
            dsum = ((aa.x + aa.y) + (aa.z + aa.w))
                 + ((bb.x + bb.y) + (bb.z + bb.w));
        }
        // id = row + 4*dot: lane r<4 gathers d1 (r+4) and d2 (r+8).
        const float d1g = __shfl_sync(FULL, dsum, (lane & 3) + 4);
        const float d2g = __shfl_sync(FULL, dsum, (lane & 3) + 8);
        const float a1v = 1.0f + dsum;          // dsum = d0 on lanes 0..3
        const float s1v = fmaf(a1v, d1g, c1);
        const float a2v = a1v + s1v;
        const float s2v = fmaf(a2v, d2g, c2);
        const float a3v = a2v + s2v;            // valid on lanes 0..3

        // Epilogue: out = x0 * a3 + B.
        const float4 Bv = sB[tid];
#pragma unroll
        for (int r = 0; r < RPI; r++) {
            const float a3 = __shfl_sync(FULL, a3v, r);
            float4 o;
            o.x = fmaf(xr[rb + r].x, a3, Bv.x);
            o.y = fmaf(xr[rb + r].y, a3, Bv.y);
            o.z = fmaf(xr[rb + r].z, a3, Bv.z);
            o.w = fmaf(xr[rb + r].w, a3, Bv.w);
            op[(rb + r) * F4] = o;
        }
    }
}

extern "C" void kernel_launch(void* const* d_in, const int* in_sizes, int n_in,
                              void* d_out, int out_size)
{
    const float4* x = (const float4*)d_in[0];
    const float*  w = (const float*)d_in[1];   // [3,1024,1]
    const float*  b = (const float*)d_in[2];   // [3,1024,1]
    float4* out = (float4*)d_out;

    const int n_rows = in_sizes[0] / F_DIM;                           // 16384
    const int grid   = (n_rows + ROWS_PER_BLOCK - 1) / ROWS_PER_BLOCK; // 2048

    cross_layer_kernel<<<grid, 256>>>(x, w, b, out);
}

// round 12
// speedup vs baseline: 1.1130x; 1.1130x over previous
#include <cuda_runtime.h>

// DCN CrossLayer closed form: out = x0 * a3 + (b0+b1+b2), with
//   d_l = dot(x0, w_l), c1 = dot(b0,w1), c2 = dot(b0+b1,w2),
//   a1 = 1+d0; s1 = a1*d1+c1; a2 = a1+s1; s2 = a2*d2+c2; a3 = a2+s2.
//
// Single-wave persistent-style grid: 512 CTAs (<= 148 SMs x 4 CTAs), each
// handling 32 rows as 8 software-pipelined iterations of 4 rows. Next
// iteration's 4 LDG.128 are issued before the current butterfly/sync chain,
// so DRAM loads stay continuously in flight. x/out use streaming (.cs)
// hints; w register-resident; B in smem. 13-SHFL batched butterfly.

#define F_DIM 1024
#define F4    256
#define RPI   4
#define ROWS_PER_BLOCK 32
#define N_ITERS (ROWS_PER_BLOCK / RPI)   // 8
#define FULL  0xffffffffu

__device__ __forceinline__ float dot4(float4 a, float4 b) {
    float acc = a.x * b.x;
    acc = fmaf(a.y, b.y, acc);
    acc = fmaf(a.z, b.z, acc);
    return fmaf(a.w, b.w, acc);
}

__device__ __forceinline__ float pair_step(float a, float b, int off, int lane) {
    const bool hi = (lane & off) != 0;
    float keep = hi ? b : a;
    float send = hi ? a : b;
    return keep + __shfl_xor_sync(FULL, send, off);
}

__global__ void __launch_bounds__(256, 4)
cross_layer_kernel(const float4* __restrict__ x,
                   const float*  __restrict__ w,   // [3,1024]
                   const float*  __restrict__ b,   // [3,1024]
                   float4* __restrict__ out)
{
    __shared__ float  sPf[2][12 * 8];  // [iter-parity][sum_id][warp]
    __shared__ float4 sB[F4];          // b0+b1+b2 per feature chunk
    __shared__ float2 sC[8];           // (c1,c2) warp partials

    const int tid  = threadIdx.x;
    const int lane = tid & 31;
    const int wid  = tid >> 5;

    // ---- Register-resident weights at this thread's feature chunk ----
    const float4 w0 = __ldg(&((const float4*)(w))[tid]);
    const float4 w1 = __ldg(&((const float4*)(w + F_DIM))[tid]);
    const float4 w2 = __ldg(&((const float4*)(w + 2 * F_DIM))[tid]);

    // ---- Prologue: B -> smem, c1/c2 block scalars. ----
    {
        const float4 b0v = __ldg(&((const float4*)(b))[tid]);
        const float4 b1v = __ldg(&((const float4*)(b + F_DIM))[tid]);
        const float4 b2v = __ldg(&((const float4*)(b + 2 * F_DIM))[tid]);
        float4 b01, B;
        b01.x = b0v.x + b1v.x;  b01.y = b0v.y + b1v.y;
        b01.z = b0v.z + b1v.z;  b01.w = b0v.w + b1v.w;
        B.x = b01.x + b2v.x;    B.y = b01.y + b2v.y;
        B.z = b01.z + b2v.z;    B.w = b01.w + b2v.w;
        sB[tid] = B;

        float q = pair_step(dot4(b0v, w1), dot4(b01, w2), 16, lane);
#pragma unroll
        for (int o = 8; o; o >>= 1) q += __shfl_xor_sync(FULL, q, o);
        if (lane == 0)  sC[wid].x = q;
        if (lane == 16) sC[wid].y = q;
    }
    __syncthreads();

    float c1 = 0.0f, c2 = 0.0f;
#pragma unroll
    for (int i = 0; i < 8; i++) { float2 v = sC[i]; c1 += v.x; c2 += v.y; }

    const size_t base = (size_t)blockIdx.x * ROWS_PER_BLOCK * F4 + tid;
    const float4* __restrict__ xp = x + base;
    float4*       __restrict__ op = out + base;

    // ---- Pipelined main loop: prefetch iter i+1 during iter i's work ----
    float4 xr[RPI], xn[RPI];
#pragma unroll
    for (int r = 0; r < RPI; r++)
        xr[r] = __ldcs(xp + r * F4);

    for (int it = 0; it < N_ITERS; it++) {
        float* __restrict__ sP = sPf[it & 1];
        const int rb = it * RPI;

        // Prefetch next 4 rows (overlaps the butterfly/sync/epilogue below).
        if (it < N_ITERS - 1) {
#pragma unroll
            for (int r = 0; r < RPI; r++)
                xn[r] = __ldcs(xp + (rb + RPI + r) * F4);
        }

        // 12 per-thread partials, ordered id = row + 4*dot.
        float p[12];
#pragma unroll
        for (int r = 0; r < RPI; r++) {
            p[r + 0] = dot4(xr[r], w0);
            p[r + 4] = dot4(xr[r], w1);
            p[r + 8] = dot4(xr[r], w2);
        }

        // Batched butterfly: 13 SHFLs reduce all 12 scalars.
        float u0 = pair_step(p[0],  p[1],  16, lane);
        float u1 = pair_step(p[2],  p[3],  16, lane);
        float u2 = pair_step(p[4],  p[5],  16, lane);
        float u3 = pair_step(p[6],  p[7],  16, lane);
        float u4 = pair_step(p[8],  p[9],  16, lane);
        float u5 = pair_step(p[10], p[11], 16, lane);
        float t0 = pair_step(u0, u1, 8, lane);
        float t1 = pair_step(u2, u3, 8, lane);
        float t2 = pair_step(u4, u5, 8, lane);
        float s0 = pair_step(t0, t1, 4, lane);
        float s1 = t2 + __shfl_xor_sync(FULL, t2, 4);
        float q  = pair_step(s0, s1, 2, lane);
        q += __shfl_xor_sync(FULL, q, 1);

        // Lane -> slot mapping (verified R6/R9/R10):
        //   b1==0: slot = 4*b2 + 2*b3 + b4 ; b1==1: slot = 8 + 2*b3 + b4
        const int b4 = (lane >> 4) & 1, b3 = (lane >> 3) & 1;
        const int b2i = (lane >> 2) & 1, b1i = (lane >> 1) & 1, b0i = lane & 1;
        const int  slot   = b1i ? (8 + 2 * b3 + b4) : (4 * b2i + 2 * b3 + b4);
        const bool writer = (b0i == 0) && (b1i == 0 || b2i == 0);
        if (writer) sP[slot * 8 + wid] = q;
        __syncthreads();

        // Stage-2 per warp: lane k (k<12) sums 8 warp-partials of id k.
        float dsum = 0.0f;
        if (lane < 12) {
            const float4* pp = (const float4*)(sP + lane * 8);
            float4 aa = pp[0], bb = pp[1];
            dsum = ((aa.x + aa.y) + (aa.z + aa.w))
                 + ((bb.x + bb.y) + (bb.z + bb.w));
        }
        // id = row + 4*dot: lane r<4 gathers d1 (r+4), d2 (r+8).
        const float d1g = __shfl_sync(FULL, dsum, (lane & 3) + 4);
        const float d2g = __shfl_sync(FULL, dsum, (lane & 3) + 8);
        const float a1v = 1.0f + dsum;           // dsum = d0 on lanes 0..3
        const float s1v = fmaf(a1v, d1g, c1);
        const float a2v = a1v + s1v;
        const float s2v = fmaf(a2v, d2g, c2);
        const float a3v = a2v + s2v;             // valid on lanes 0..3

        // Epilogue: out = x0 * a3 + B (streaming stores).
        const float4 Bv = sB[tid];
#pragma unroll
        for (int r = 0; r < RPI; r++) {
            const float a3 = __shfl_sync(FULL, a3v, r);
            float4 o;
            o.x = fmaf(xr[r].x, a3, Bv.x);
            o.y = fmaf(xr[r].y, a3, Bv.y);
            o.z = fmaf(xr[r].z, a3, Bv.z);
            o.w = fmaf(xr[r].w, a3, Bv.w);
            __stcs(op + (rb + r) * F4, o);
        }

#pragma unroll
        for (int r = 0; r < RPI; r++) xr[r] = xn[r];
    }
}

extern "C" void kernel_launch(void* const* d_in, const int* in_sizes, int n_in,
                              void* d_out, int out_size)
{
    const float4* x = (const float4*)d_in[0];
    const float*  w = (const float*)d_in[1];   // [3,1024,1]
    const float*  b = (const float*)d_in[2];   // [3,1024,1]
    float4* out = (float4*)d_out;

    const int n_rows = in_sizes[0] / F_DIM;                            // 16384
    const int grid   = (n_rows + ROWS_PER_BLOCK - 1) / ROWS_PER_BLOCK; // 512

    cross_layer_kernel<<<grid, 256>>>(x, w, b, out);
}

// round 14
// speedup vs baseline: 1.1963x; 1.0749x over previous
#include <cuda_runtime.h>

// DCN CrossLayer closed form: out = x0 * a3 + (b0+b1+b2), with
//   d_l = dot(x0, w_l), c1 = dot(b0,w1), c2 = dot(b0+b1,w2),
//   a1 = 1+d0; s1 = a1*d1+c1; a2 = a1+s1; s2 = a2*d2+c2; a3 = a2+s2.
//
// Persistent tile-strided grid: 608 CTAs (152 SMs x 4 resident CTAs), each
// looping over 4-row tiles with stride 608 -> near-perfect SM load balance
// (no wave quantization). Software pipeline: next tile's 4 LDG.128 issued
// before the current butterfly/sync chain. x/out streaming (.cs); w in
// registers; B in smem. Batched 13-SHFL butterfly (verified R6-R11).

#define F_DIM 1024
#define F4    256
#define RPI   4
#define N_CTAS 608
#define FULL  0xffffffffu

__device__ __forceinline__ float dot4(float4 a, float4 b) {
    float acc = a.x * b.x;
    acc = fmaf(a.y, b.y, acc);
    acc = fmaf(a.z, b.z, acc);
    return fmaf(a.w, b.w, acc);
}

__device__ __forceinline__ float pair_step(float a, float b, int off, int lane) {
    const bool hi = (lane & off) != 0;
    float keep = hi ? b : a;
    float send = hi ? a : b;
    return keep + __shfl_xor_sync(FULL, send, off);
}

__global__ void __launch_bounds__(256, 4)
cross_layer_kernel(const float4* __restrict__ x,
                   const float*  __restrict__ w,   // [3,1024]
                   const float*  __restrict__ b,   // [3,1024]
                   float4* __restrict__ out,
                   int n_tiles)
{
    __shared__ float  sPf[2][12 * 8];  // [tile-parity][sum_id][warp]
    __shared__ float4 sB[F4];          // b0+b1+b2 per feature chunk
    __shared__ float2 sC[8];           // (c1,c2) warp partials

    const int tid  = threadIdx.x;
    const int lane = tid & 31;
    const int wid  = tid >> 5;

    // ---- Register-resident weights at this thread's feature chunk ----
    const float4 w0 = __ldg(&((const float4*)(w))[tid]);
    const float4 w1 = __ldg(&((const float4*)(w + F_DIM))[tid]);
    const float4 w2 = __ldg(&((const float4*)(w + 2 * F_DIM))[tid]);

    // ---- Prologue: B -> smem, c1/c2 block scalars. ----
    {
        const float4 b0v = __ldg(&((const float4*)(b))[tid]);
        const float4 b1v = __ldg(&((const float4*)(b + F_DIM))[tid]);
        const float4 b2v = __ldg(&((const float4*)(b + 2 * F_DIM))[tid]);
        float4 b01, B;
        b01.x = b0v.x + b1v.x;  b01.y = b0v.y + b1v.y;
        b01.z = b0v.z + b1v.z;  b01.w = b0v.w + b1v.w;
        B.x = b01.x + b2v.x;    B.y = b01.y + b2v.y;
        B.z = b01.z + b2v.z;    B.w = b01.w + b2v.w;
        sB[tid] = B;

        float q = pair_step(dot4(b0v, w1), dot4(b01, w2), 16, lane);
#pragma unroll
        for (int o = 8; o; o >>= 1) q += __shfl_xor_sync(FULL, q, o);
        if (lane == 0)  sC[wid].x = q;
        if (lane == 16) sC[wid].y = q;
    }
    __syncthreads();

    float c1 = 0.0f, c2 = 0.0f;
#pragma unroll
    for (int i = 0; i < 8; i++) { float2 v = sC[i]; c1 += v.x; c2 += v.y; }

    // ---- Persistent tile loop with software pipeline ----
    // Tile t covers rows [t*4, t*4+4). Thread offset tid within each row.
    int tile = blockIdx.x;
    if (tile >= n_tiles) return;

    const size_t tile_stride = (size_t)RPI * F4;   // float4s per tile

    float4 xr[RPI], xn[RPI];
    {
        const float4* __restrict__ xp = x + (size_t)tile * tile_stride + tid;
#pragma unroll
        for (int r = 0; r < RPI; r++)
            xr[r] = __ldcs(xp + r * F4);
    }

    int parity = 0;
    for (; tile < n_tiles; tile += N_CTAS, parity ^= 1) {
        float* __restrict__ sP = sPf[parity];
        const int next = tile + N_CTAS;

        // Prefetch next tile's 4 rows (overlaps butterfly/sync/epilogue).
        if (next < n_tiles) {
            const float4* __restrict__ xq = x + (size_t)next * tile_stride + tid;
#pragma unroll
            for (int r = 0; r < RPI; r++)
                xn[r] = __ldcs(xq + r * F4);
        }

        // 12 per-thread partials, ordered id = row + 4*dot.
        float p[12];
#pragma unroll
        for (int r = 0; r < RPI; r++) {
            p[r + 0] = dot4(xr[r], w0);
            p[r + 4] = dot4(xr[r], w1);
            p[r + 8] = dot4(xr[r], w2);
        }

        // Batched butterfly: 13 SHFLs reduce all 12 scalars.
        float u0 = pair_step(p[0],  p[1],  16, lane);
        float u1 = pair_step(p[2],  p[3],  16, lane);
        float u2 = pair_step(p[4],  p[5],  16, lane);
        float u3 = pair_step(p[6],  p[7],  16, lane);
        float u4 = pair_step(p[8],  p[9],  16, lane);
        float u5 = pair_step(p[10], p[11], 16, lane);
        float t0 = pair_step(u0, u1, 8, lane);
        float t1 = pair_step(u2, u3, 8, lane);
        float t2 = pair_step(u4, u5, 8, lane);
        float s0 = pair_step(t0, t1, 4, lane);
        float s1 = t2 + __shfl_xor_sync(FULL, t2, 4);
        float q  = pair_step(s0, s1, 2, lane);
        q += __shfl_xor_sync(FULL, q, 1);

        // Lane -> slot mapping (verified R6-R11):
        //   b1==0: slot = 4*b2 + 2*b3 + b4 ; b1==1: slot = 8 + 2*b3 + b4
        const int b4 = (lane >> 4) & 1, b3 = (lane >> 3) & 1;
        const int b2i = (lane >> 2) & 1, b1i = (lane >> 1) & 1, b0i = lane & 1;
        const int  slot   = b1i ? (8 + 2 * b3 + b4) : (4 * b2i + 2 * b3 + b4);
        const bool writer = (b0i == 0) && (b1i == 0 || b2i == 0);
        if (writer) sP[slot * 8 + wid] = q;
        __syncthreads();

        // Stage-2 per warp: lane k (k<12) sums 8 warp-partials of id k.
        float dsum = 0.0f;
        if (lane < 12) {
            const float4* pp = (const float4*)(sP + lane * 8);
            float4 aa = pp[0], bb = pp[1];
            dsum = ((aa.x + aa.y) + (aa.z + aa.w))
                 + ((bb.x + bb.y) + (bb.z + bb.w));
        }
        // id = row + 4*dot: lane r<4 gathers d1 (r+4), d2 (r+8).
        const float d1g = __shfl_sync(FULL, dsum, (lane & 3) + 4);
        const float d2g = __shfl_sync(FULL, dsum, (lane & 3) + 8);
        const float a1v = 1.0f + dsum;           // dsum = d0 on lanes 0..3
        const float s1v = fmaf(a1v, d1g, c1);
        const float a2v = a1v + s1v;
        const float s2v = fmaf(a2v, d2g, c2);
        const float a3v = a2v + s2v;             // valid on lanes 0..3

        // Epilogue: out = x0 * a3 + B (streaming stores).
        const float4 Bv = sB[tid];
        float4* __restrict__ op = out + (size_t)tile * tile_stride + tid;
#pragma unroll
        for (int r = 0; r < RPI; r++) {
            const float a3 = __shfl_sync(FULL, a3v, r);
            float4 o;
            o.x = fmaf(xr[r].x, a3, Bv.x);
            o.y = fmaf(xr[r].y, a3, Bv.y);
            o.z = fmaf(xr[r].z, a3, Bv.z);
            o.w = fmaf(xr[r].w, a3, Bv.w);
            __stcs(op + r * F4, o);
        }

#pragma unroll
        for (int r = 0; r < RPI; r++) xr[r] = xn[r];
    }
}

extern "C" void kernel_launch(void* const* d_in, const int* in_sizes, int n_in,
                              void* d_out, int out_size)
{
    const float4* x = (const float4*)d_in[0];
    const float*  w = (const float*)d_in[1];   // [3,1024,1]
    const float*  b = (const float*)d_in[2];   // [3,1024,1]
    float4* out = (float4*)d_out;

    const int n_rows  = in_sizes[0] / F_DIM;   // 16384
    const int n_tiles = n_rows / RPI;          // 4096

    cross_layer_kernel<<<N_CTAS, 256>>>(x, w, b, out, n_tiles);
}

// round 16
// speedup vs baseline: 1.2931x; 1.0809x over previous
#include <cuda_runtime.h>
#include <cstdint>

// DCN CrossLayer closed form: out = x0 * a3 + (b0+b1+b2), with
//   d_l = dot(x0, w_l), c1 = dot(b0,w1), c2 = dot(b0+b1,w2),
//   a1 = 1+d0; s1 = a1*d1+c1; a2 = a1+s1; s2 = a2*d2+c2; a3 = a2+s2.
//
// Persistent 608-CTA grid (152 SMs x 4), tile = 4 rows, stride 608.
// x streamed via cp.async.cg into a 3-stage PRIVATE smem ring (each thread
// consumes exactly what it fetched -> no ring barriers; wait_group only).
// Lookahead = 2 tile-groups in flight (128 KB/SM) at zero register cost.
// R14 fix: opt in to >48KB dynamic smem via cudaFuncSetAttribute (static
// sPf/sC pushed dyn+static past the default 48 KB cap -> launch failure).

#define F_DIM 1024
#define F4    256
#define RPI   4
#define NSTAGE 3
#define N_CTAS 608
#define FULL  0xffffffffu

__device__ __forceinline__ void cp_async16(uint32_t saddr, const void* gptr) {
    asm volatile("cp.async.cg.shared.global [%0], [%1], 16;"
                 :: "r"(saddr), "l"(gptr) : "memory");
}
__device__ __forceinline__ void cp_commit() {
    asm volatile("cp.async.commit_group;" ::: "memory");
}
__device__ __forceinline__ void cp_wait2() {
    asm volatile("cp.async.wait_group 2;" ::: "memory");
}

__device__ __forceinline__ float dot4(float4 a, float4 b) {
    float acc = a.x * b.x;
    acc = fmaf(a.y, b.y, acc);
    acc = fmaf(a.z, b.z, acc);
    return fmaf(a.w, b.w, acc);
}

__device__ __forceinline__ float pair_step(float a, float b, int off, int lane) {
    const bool hi = (lane & off) != 0;
    float keep = hi ? b : a;
    float send = hi ? a : b;
    return keep + __shfl_xor_sync(FULL, send, off);
}

extern __shared__ float4 ring[];   // NSTAGE * RPI * 256 float4 = 48 KB

__global__ void __launch_bounds__(256, 4)
cross_layer_kernel(const float4* __restrict__ x,
                   const float*  __restrict__ w,   // [3,1024]
                   const float*  __restrict__ b,   // [3,1024]
                   float4* __restrict__ out,
                   int n_tiles)
{
    __shared__ float  sPf[2][12 * 8];  // [tile-parity][sum_id][warp]
    __shared__ float2 sC[8];           // (c1,c2) warp partials

    const int tid  = threadIdx.x;
    const int lane = tid & 31;
    const int wid  = tid >> 5;

    // ---- Register-resident weights / bias at this thread's chunk ----
    const float4 w0 = __ldg(&((const float4*)(w))[tid]);
    const float4 w1 = __ldg(&((const float4*)(w + F_DIM))[tid]);
    const float4 w2 = __ldg(&((const float4*)(w + 2 * F_DIM))[tid]);

    float4 Bv;
    float c1, c2;
    {
        const float4 b0v = __ldg(&((const float4*)(b))[tid]);
        const float4 b1v = __ldg(&((const float4*)(b + F_DIM))[tid]);
        const float4 b2v = __ldg(&((const float4*)(b + 2 * F_DIM))[tid]);
        float4 b01;
        b01.x = b0v.x + b1v.x;  b01.y = b0v.y + b1v.y;
        b01.z = b0v.z + b1v.z;  b01.w = b0v.w + b1v.w;
        Bv.x = b01.x + b2v.x;   Bv.y = b01.y + b2v.y;
        Bv.z = b01.z + b2v.z;   Bv.w = b01.w + b2v.w;

        float q = pair_step(dot4(b0v, w1), dot4(b01, w2), 16, lane);
#pragma unroll
        for (int o = 8; o; o >>= 1) q += __shfl_xor_sync(FULL, q, o);
        if (lane == 0)  sC[wid].x = q;
        if (lane == 16) sC[wid].y = q;
        __syncthreads();
        c1 = 0.0f; c2 = 0.0f;
#pragma unroll
        for (int i = 0; i < 8; i++) { float2 v = sC[i]; c1 += v.x; c2 += v.y; }
    }

    // ---- Async ring: thread-private slots ----
    // Slot (stage, r) for this thread: ring[(stage*RPI + r)*256 + tid].
    const uint32_t ring_base =
        (uint32_t)__cvta_generic_to_shared(ring) + (uint32_t)tid * 16u;
    const size_t tile_stride = (size_t)RPI * F4;   // float4s per tile

    const int tile0 = blockIdx.x;
    if (tile0 >= n_tiles) return;

    // Prologue: issue up to 3 tile-groups.
#pragma unroll
    for (int k = 0; k < NSTAGE; k++) {
        const int t = tile0 + k * N_CTAS;
        if (t < n_tiles) {
            const float4* gp = x + (size_t)t * tile_stride + tid;
#pragma unroll
            for (int r = 0; r < RPI; r++)
                cp_async16(ring_base + (uint32_t)((k * RPI + r) * 256) * 16u,
                           gp + r * F4);
        }
        cp_commit();
    }

    int parity = 0;
    int stage  = 0;
    for (int tile = tile0; tile < n_tiles; tile += N_CTAS, parity ^= 1) {
        float* __restrict__ sP = sPf[parity];

        // Oldest group complete -> this thread's stage data valid.
        cp_wait2();

        // Pull the 4 row-chunks into registers (LDS, ~29 cyc).
        float4 xr[RPI];
#pragma unroll
        for (int r = 0; r < RPI; r++)
            xr[r] = ring[(stage * RPI + r) * 256 + tid];

        // 12 per-thread partials, ordered id = row + 4*dot.
        float p[12];
#pragma unroll
        for (int r = 0; r < RPI; r++) {
            p[r + 0] = dot4(xr[r], w0);
            p[r + 4] = dot4(xr[r], w1);
            p[r + 8] = dot4(xr[r], w2);
        }

        // Refill the freed stage (dots done => LDS drained; x in regs).
        {
            const int t = tile + NSTAGE * N_CTAS;
            if (t < n_tiles) {
                const float4* gp = x + (size_t)t * tile_stride + tid;
#pragma unroll
                for (int r = 0; r < RPI; r++)
                    cp_async16(ring_base + (uint32_t)((stage * RPI + r) * 256) * 16u,
                               gp + r * F4);
            }
            cp_commit();
        }

        // Batched butterfly: 13 SHFLs reduce all 12 scalars.
        float u0 = pair_step(p[0],  p[1],  16, lane);
        float u1 = pair_step(p[2],  p[3],  16, lane);
        float u2 = pair_step(p[4],  p[5],  16, lane);
        float u3 = pair_step(p[6],  p[7],  16, lane);
        float u4 = pair_step(p[8],  p[9],  16, lane);
        float u5 = pair_step(p[10], p[11], 16, lane);
        float t0 = pair_step(u0, u1, 8, lane);
        float t1 = pair_step(u2, u3, 8, lane);
        float t2 = pair_step(u4, u5, 8, lane);
        float s0 = pair_step(t0, t1, 4, lane);
        float s1 = t2 + __shfl_xor_sync(FULL, t2, 4);
        float q  = pair_step(s0, s1, 2, lane);
        q += __shfl_xor_sync(FULL, q, 1);

        // Lane -> slot mapping (verified R6-R12):
        //   b1==0: slot = 4*b2 + 2*b3 + b4 ; b1==1: slot = 8 + 2*b3 + b4
        const int b4 = (lane >> 4) & 1, b3 = (lane >> 3) & 1;
        const int b2i = (lane >> 2) & 1, b1i = (lane >> 1) & 1, b0i = lane & 1;
        const int  slot   = b1i ? (8 + 2 * b3 + b4) : (4 * b2i + 2 * b3 + b4);
        const bool writer = (b0i == 0) && (b1i == 0 || b2i == 0);
        if (writer) sP[slot * 8 + wid] = q;
        __syncthreads();

        // Stage-2 per warp: lane k (k<12) sums 8 warp-partials of id k.
        float dsum = 0.0f;
        if (lane < 12) {
            const float4* pp = (const float4*)(sP + lane * 8);
            float4 aa = pp[0], bb = pp[1];
            dsum = ((aa.x + aa.y) + (aa.z + aa.w))
                 + ((bb.x + bb.y) + (bb.z + bb.w));
        }
        // id = row + 4*dot: lane r<4 gathers d1 (r+4), d2 (r+8).
        const float d1g = __shfl_sync(FULL, dsum, (lane & 3) + 4);
        const float d2g = __shfl_sync(FULL, dsum, (lane & 3) + 8);
        const float a1v = 1.0f + dsum;           // dsum = d0 on lanes 0..3
        const float s1v = fmaf(a1v, d1g, c1);
        const float a2v = a1v + s1v;
        const float s2v = fmaf(a2v, d2g, c2);
        const float a3v = a2v + s2v;             // valid on lanes 0..3

        // Epilogue: out = x0 * a3 + B (streaming stores).
        float4* __restrict__ op = out + (size_t)tile * tile_stride + tid;
#pragma unroll
        for (int r = 0; r < RPI; r++) {
            const float a3 = __shfl_sync(FULL, a3v, r);
            float4 o;
            o.x = fmaf(xr[r].x, a3, Bv.x);
            o.y = fmaf(xr[r].y, a3, Bv.y);
            o.z = fmaf(xr[r].z, a3, Bv.z);
            o.w = fmaf(xr[r].w, a3, Bv.w);
            __stcs(op + r * F4, o);
        }

        stage = (stage == NSTAGE - 1) ? 0 : stage + 1;
    }
}

extern "C" void kernel_launch(void* const* d_in, const int* in_sizes, int n_in,
                              void* d_out, int out_size)
{
    const float4* x = (const float4*)d_in[0];
    const float*  w = (const float*)d_in[1];   // [3,1024,1]
    const float*  b = (const float*)d_in[2];   // [3,1024,1]
    float4* out = (float4*)d_out;

    const int n_rows  = in_sizes[0] / F_DIM;   // 16384
    const int n_tiles = n_rows / RPI;          // 4096

    const int smem = NSTAGE * RPI * 256 * sizeof(float4);   // 49152 B dynamic

    // Opt in to >48KB dynamic smem (R14 failed without this: dyn + static
    // statics exceeded the default cap). Host attribute call — capture-legal.
    cudaFuncSetAttribute(cross_layer_kernel,
                         cudaFuncAttributeMaxDynamicSharedMemorySize,
                         56 * 1024);

    cross_layer_kernel<<<N_CTAS, 256, smem>>>(x, w, b, out, n_tiles);
}